// round 15
// baseline (speedup 1.0000x reference)
#include <cuda_runtime.h>
#include <cuda_fp16.h>
#include <cstdint>

// ---------------- problem shape ----------------
#define M_DIM 4096
#define K_DIM 4096
#define N_DIM 11008

// int8 scratch (device globals: allocation-free scratch)
__device__ __align__(128) static int8_t g_A8[(size_t)M_DIM * K_DIM];   // 16.8 MB
__device__ __align__(128) static int8_t g_B8[(size_t)N_DIM * K_DIM];   // 45.1 MB

// ---------------- helpers ----------------
__device__ __forceinline__ uint32_t smem_to_u32(const void* smem_ptr) {
    uint32_t addr;
    asm("{ .reg .u64 tmp; cvta.to.shared.u64 tmp, %1; cvt.u32.u64 %0, tmp; }"
        : "=r"(addr) : "l"(smem_ptr));
    return addr;
}

__device__ __forceinline__ void cp_async8(uint32_t dst_smem, const void* src_gmem) {
    asm volatile("cp.async.ca.shared.global [%0], [%1], 8;"
                 :: "r"(dst_smem), "l"(src_gmem) : "memory");
}
__device__ __forceinline__ void cp_commit() {
    asm volatile("cp.async.commit_group;" ::: "memory");
}
template <int N>
__device__ __forceinline__ void cp_wait_group() {
    asm volatile("cp.async.wait_group %0;" :: "n"(N) : "memory");
}

__device__ __forceinline__ void mma_s8(int* c, const uint32_t* a, const uint32_t* b) {
    asm volatile(
        "mma.sync.aligned.m16n8k32.row.col.s32.s8.s8.s32 "
        "{%0,%1,%2,%3}, {%4,%5,%6,%7}, {%8,%9}, {%0,%1,%2,%3};"
        : "+r"(c[0]), "+r"(c[1]), "+r"(c[2]), "+r"(c[3])
        : "r"(a[0]), "r"(a[1]), "r"(a[2]), "r"(a[3]), "r"(b[0]), "r"(b[1]));
}

// smem swizzle: row-major [row][64 bytes of K], 8B granules XORed by row&7
// (conflict-free for the 4B fragment loads below)
__device__ __forceinline__ uint32_t sw_off(int row, int k) {
    return (uint32_t)(row * 64 + ((((k >> 3) ^ (row & 7))) << 3) + (k & 7));
}

// ---------------- unpack: packed int4 (one byte per int32) -> int8 ----------------
__device__ __forceinline__ void unpack_body(const int* __restrict__ in,
                                            int8_t* __restrict__ outp, long long n4)
{
    long long idx = (long long)blockIdx.x * blockDim.x + threadIdx.x;
    if (idx >= n4) return;
    int4 v = reinterpret_cast<const int4*>(in)[idx];
    int bs[4] = { v.x & 0xFF, v.y & 0xFF, v.z & 0xFF, v.w & 0xFF };
    uint32_t lo32 = 0, hi32 = 0;
    #pragma unroll
    for (int i = 0; i < 2; ++i) {
        int b = bs[i];
        int l = ((b & 0xF) ^ 8) - 8;         // sign-extended low nibble  (k even)
        int h = ((b >> 4) ^ 8) - 8;          // sign-extended high nibble (k odd)
        lo32 |= ((uint32_t)(l & 0xFF)) << (i * 16);
        lo32 |= ((uint32_t)(h & 0xFF)) << (i * 16 + 8);
    }
    #pragma unroll
    for (int i = 0; i < 2; ++i) {
        int b = bs[2 + i];
        int l = ((b & 0xF) ^ 8) - 8;
        int h = ((b >> 4) ^ 8) - 8;
        hi32 |= ((uint32_t)(l & 0xFF)) << (i * 16);
        hi32 |= ((uint32_t)(h & 0xFF)) << (i * 16 + 8);
    }
    uint2 r = make_uint2(lo32, hi32);
    reinterpret_cast<uint2*>(outp)[idx] = r;
}

__global__ void unpackA_kernel(const int* __restrict__ in, long long n4) {
    unpack_body(in, g_A8, n4);
}
__global__ void unpackB_kernel(const int* __restrict__ in, long long n4) {
    unpack_body(in, g_B8, n4);
}

// ---------------- GEMM ----------------
// CTA tile 128(M) x 256(N), 256 threads = 8 warps (2 x 4), warp tile 64 x 64.
// K staged in 64-byte slices, 4-stage cp.async pipeline.
static constexpr int TILE_M  = 128;
static constexpr int TILE_N  = 256;
static constexpr int KS      = 64;                    // K bytes per stage
static constexpr int N_ITERS = K_DIM / KS;            // 64
static constexpr int STAGES  = 4;
static constexpr int A_STG_B = TILE_M * KS;           // 8192
static constexpr int B_STG_B = TILE_N * KS;           // 16384
static constexpr int STG_B   = A_STG_B + B_STG_B;     // 24576
static constexpr int SMEM_TOTAL = STAGES * STG_B;     // 98304

__global__ void __launch_bounds__(256, 1)
gemm_kernel(const float* __restrict__ sx, const float* __restrict__ ws,
            float* __restrict__ out)
{
    extern __shared__ char smem[];
    uint32_t sbase = smem_to_u32(smem);

    int tid  = threadIdx.x;
    int warp = tid >> 5;
    int lane = tid & 31;
    int wm = warp >> 2;          // 0..1  (M direction, 64 rows each)
    int wn = warp & 3;           // 0..3  (N direction, 64 cols each)
    int g  = lane >> 2;          // 0..7
    int t  = lane & 3;           // 0..3

    int n0 = blockIdx.x * TILE_N;
    int m0 = blockIdx.y * TILE_M;

    const int8_t* gA = g_A8 + (size_t)m0 * K_DIM;
    const int8_t* gB = g_B8 + (size_t)n0 * K_DIM;

    int acc[4][8][4];
    #pragma unroll
    for (int mb = 0; mb < 4; ++mb)
        #pragma unroll
        for (int nb = 0; nb < 8; ++nb)
            #pragma unroll
            for (int r = 0; r < 4; ++r) acc[mb][nb][r] = 0;

    // producer: 12 x 8B chunks per thread per stage (A: 4, B: 8)
    auto copy_stage = [&](int s, int kbase) {
        uint32_t sA = sbase + (uint32_t)s * STG_B;
        uint32_t sB = sA + A_STG_B;
        #pragma unroll
        for (int i = 0; i < 4; ++i) {
            int c = tid + i * 256;              // 0..1023
            int row = c >> 3, k8 = c & 7;
            cp_async8(sA + (uint32_t)(row * 64 + ((k8 ^ (row & 7)) << 3)),
                      gA + (size_t)row * K_DIM + kbase + k8 * 8);
        }
        #pragma unroll
        for (int i = 0; i < 8; ++i) {
            int c = tid + i * 256;              // 0..2047
            int row = c >> 3, k8 = c & 7;
            cp_async8(sB + (uint32_t)(row * 64 + ((k8 ^ (row & 7)) << 3)),
                      gB + (size_t)row * K_DIM + kbase + k8 * 8);
        }
    };

    // prologue: fill STAGES-1 stages
    #pragma unroll
    for (int s = 0; s < STAGES - 1; ++s) {
        copy_stage(s, s * KS);
        cp_commit();
    }

    for (int it = 0; it < N_ITERS; ++it) {
        int s = it & (STAGES - 1);
        cp_wait_group<STAGES - 2>();
        __syncthreads();

        uint32_t sA = sbase + (uint32_t)s * STG_B;
        uint32_t sB = sA + A_STG_B;

        #pragma unroll
        for (int kb = 0; kb < 2; ++kb) {
            int k32 = kb * 32;
            // A fragments: 4 m-blocks x 4 regs
            uint32_t afr[4][4];
            #pragma unroll
            for (int mb = 0; mb < 4; ++mb) {
                int r0 = wm * 64 + mb * 16 + g;
                afr[mb][0] = *(const uint32_t*)(smem + sA - sbase + sw_off(r0,     k32 + t * 4));
                afr[mb][1] = *(const uint32_t*)(smem + sA - sbase + sw_off(r0 + 8, k32 + t * 4));
                afr[mb][2] = *(const uint32_t*)(smem + sA - sbase + sw_off(r0,     k32 + 16 + t * 4));
                afr[mb][3] = *(const uint32_t*)(smem + sA - sbase + sw_off(r0 + 8, k32 + 16 + t * 4));
            }
            // B fragments: 8 n-blocks x 2 regs
            uint32_t bfr[8][2];
            #pragma unroll
            for (int nb = 0; nb < 8; ++nb) {
                int nr = wn * 64 + nb * 8 + g;
                bfr[nb][0] = *(const uint32_t*)(smem + sB - sbase + sw_off(nr, k32 + t * 4));
                bfr[nb][1] = *(const uint32_t*)(smem + sB - sbase + sw_off(nr, k32 + 16 + t * 4));
            }
            #pragma unroll
            for (int mb = 0; mb < 4; ++mb)
                #pragma unroll
                for (int nb = 0; nb < 8; ++nb)
                    mma_s8(acc[mb][nb], afr[mb], bfr[nb]);
        }

        // refill the stage consumed at it-1 (all warps past the sync above)
        int nxt = it + STAGES - 1;
        if (nxt < N_ITERS) copy_stage(nxt & (STAGES - 1), nxt * KS);
        cp_commit();
    }

    // ---------------- epilogue ----------------
    // out = fp16_round( (acc * sx[m]) * ws[n] ) upconverted to f32 — bit-exact
    // vs the reference's f32-compute -> f16-cast -> f32-compare path.
    #pragma unroll
    for (int mb = 0; mb < 4; ++mb) {
        int r0 = m0 + wm * 64 + mb * 16 + g;
        float sx0 = sx[r0];
        float sx1 = sx[r0 + 8];
        #pragma unroll
        for (int nb = 0; nb < 8; ++nb) {
            int nc = n0 + wn * 64 + nb * 8 + t * 2;
            float w0 = ws[nc];
            float w1 = ws[nc + 1];
            float2 v0, v1;
            v0.x = __half2float(__float2half_rn(((float)acc[mb][nb][0] * sx0) * w0));
            v0.y = __half2float(__float2half_rn(((float)acc[mb][nb][1] * sx0) * w1));
            v1.x = __half2float(__float2half_rn(((float)acc[mb][nb][2] * sx1) * w0));
            v1.y = __half2float(__float2half_rn(((float)acc[mb][nb][3] * sx1) * w1));
            *reinterpret_cast<float2*>(out + (size_t)r0 * N_DIM + nc)       = v0;
            *reinterpret_cast<float2*>(out + (size_t)(r0 + 8) * N_DIM + nc) = v1;
        }
    }
}

// ---------------- launch ----------------
extern "C" void kernel_launch(void* const* d_in, const int* in_sizes, int n_in,
                              void* d_out, int out_size)
{
    const int*   x_q = (const int*)d_in[0];
    const float* sx  = (const float*)d_in[1];   // harness materializes f16 as f32
    const int*   wt  = (const int*)d_in[2];
    const float* ws  = (const float*)d_in[3];
    float*       out = (float*)d_out;           // __output__ dtype: float32

    cudaFuncSetAttribute(gemm_kernel,
                         cudaFuncAttributeMaxDynamicSharedMemorySize, SMEM_TOTAL);

    long long nA4 = (long long)M_DIM * (K_DIM / 2) / 4;   // 2,097,152
    long long nB4 = (long long)N_DIM * (K_DIM / 2) / 4;   // 5,636,096

    unpackA_kernel<<<(unsigned)((nA4 + 255) / 256), 256>>>(x_q, nA4);
    unpackB_kernel<<<(unsigned)((nB4 + 255) / 256), 256>>>(wt, nB4);

    dim3 grid(N_DIM / TILE_N, M_DIM / TILE_M);   // 43 x 32
    gemm_kernel<<<grid, 256, SMEM_TOTAL>>>(sx, ws, out);
}

// round 16
// speedup vs baseline: 1.0458x; 1.0458x over previous
#include <cuda_runtime.h>
#include <cuda_fp16.h>
#include <cstdint>

// ---------------- problem shape ----------------
#define M_DIM 4096
#define K_DIM 4096
#define N_DIM 11008

// int8 scratch (device globals: allocation-free scratch)
__device__ __align__(128) static int8_t g_A8[(size_t)M_DIM * K_DIM];   // 16.8 MB
__device__ __align__(128) static int8_t g_B8[(size_t)N_DIM * K_DIM];   // 45.1 MB

// ---------------- helpers ----------------
__device__ __forceinline__ uint32_t smem_to_u32(const void* smem_ptr) {
    uint32_t addr;
    asm("{ .reg .u64 tmp; cvta.to.shared.u64 tmp, %1; cvt.u32.u64 %0, tmp; }"
        : "=r"(addr) : "l"(smem_ptr));
    return addr;
}

__device__ __forceinline__ void cp_async16(uint32_t dst_smem, const void* src_gmem) {
    asm volatile("cp.async.cg.shared.global [%0], [%1], 16;"
                 :: "r"(dst_smem), "l"(src_gmem) : "memory");
}
__device__ __forceinline__ void cp_commit() {
    asm volatile("cp.async.commit_group;" ::: "memory");
}
template <int N>
__device__ __forceinline__ void cp_wait_group() {
    asm volatile("cp.async.wait_group %0;" :: "n"(N) : "memory");
}

__device__ __forceinline__ void mma_s8(int* c, const uint32_t* a, const uint32_t* b) {
    asm volatile(
        "mma.sync.aligned.m16n8k32.row.col.s32.s8.s8.s32 "
        "{%0,%1,%2,%3}, {%4,%5,%6,%7}, {%8,%9}, {%0,%1,%2,%3};"
        : "+r"(c[0]), "+r"(c[1]), "+r"(c[2]), "+r"(c[3])
        : "r"(a[0]), "r"(a[1]), "r"(a[2]), "r"(a[3]), "r"(b[0]), "r"(b[1]));
}

#define LDMATRIX_X4(r0, r1, r2, r3, addr) \
    asm volatile("ldmatrix.sync.aligned.m8n8.x4.shared.b16 {%0,%1,%2,%3}, [%4];" \
                 : "=r"(r0), "=r"(r1), "=r"(r2), "=r"(r3) : "r"(addr))

// 16B-granular swizzle over 64B rows: granule index XORed with (row>>1)&3.
// Conflict-free for ldmatrix 8-lane phases AND for cp.async 16B writes.
__device__ __forceinline__ uint32_t sw16(int row, int gran) {
    return (uint32_t)(row * 64 + ((gran ^ ((row >> 1) & 3)) << 4));
}

// ---------------- unpack: packed int4 (one byte per int32) -> int8 ----------------
__device__ __forceinline__ void unpack_body(const int* __restrict__ in,
                                            int8_t* __restrict__ outp, long long n4)
{
    long long idx = (long long)blockIdx.x * blockDim.x + threadIdx.x;
    if (idx >= n4) return;
    int4 v = reinterpret_cast<const int4*>(in)[idx];
    int bs[4] = { v.x & 0xFF, v.y & 0xFF, v.z & 0xFF, v.w & 0xFF };
    uint32_t lo32 = 0, hi32 = 0;
    #pragma unroll
    for (int i = 0; i < 2; ++i) {
        int b = bs[i];
        int l = ((b & 0xF) ^ 8) - 8;          // sign-extended low nibble  (k even)
        int h = ((b >> 4) ^ 8) - 8;           // sign-extended high nibble (k odd)
        lo32 |= ((uint32_t)(l & 0xFF)) << (i * 16);
        lo32 |= ((uint32_t)(h & 0xFF)) << (i * 16 + 8);
    }
    #pragma unroll
    for (int i = 0; i < 2; ++i) {
        int b = bs[2 + i];
        int l = ((b & 0xF) ^ 8) - 8;
        int h = ((b >> 4) ^ 8) - 8;
        hi32 |= ((uint32_t)(l & 0xFF)) << (i * 16);
        hi32 |= ((uint32_t)(h & 0xFF)) << (i * 16 + 8);
    }
    reinterpret_cast<uint2*>(outp)[idx] = make_uint2(lo32, hi32);
}

__global__ void unpackA_kernel(const int* __restrict__ in, long long n4) {
    unpack_body(in, g_A8, n4);
}
__global__ void unpackB_kernel(const int* __restrict__ in, long long n4) {
    unpack_body(in, g_B8, n4);
}

// ---------------- GEMM ----------------
// CTA tile 128(M) x 256(N), 512 threads = 16 warps (4 x 4), warp tile 32 x 64.
// K staged in 64-byte slices, 4-stage cp.async pipeline, ldmatrix fragments.
static constexpr int TILE_M  = 128;
static constexpr int TILE_N  = 256;
static constexpr int KS      = 64;                    // K bytes per stage
static constexpr int N_ITERS = K_DIM / KS;            // 64
static constexpr int STAGES  = 4;
static constexpr int A_STG_B = TILE_M * KS;           // 8192
static constexpr int B_STG_B = TILE_N * KS;           // 16384
static constexpr int STG_B   = A_STG_B + B_STG_B;     // 24576
static constexpr int SMEM_TOTAL = STAGES * STG_B;     // 98304

__global__ void __launch_bounds__(512, 1)
gemm_kernel(const float* __restrict__ sx, const float* __restrict__ ws,
            float* __restrict__ out)
{
    extern __shared__ char smem[];
    uint32_t sbase = smem_to_u32(smem);

    int tid  = threadIdx.x;
    int warp = tid >> 5;
    int lane = tid & 31;
    int wm = warp >> 2;          // 0..3  (M direction, 32 rows each)
    int wn = warp & 3;           // 0..3  (N direction, 64 cols each)
    int q  = lane >> 3;          // 0..3  (ldmatrix lane-octet)
    int r8 = lane & 7;

    int n0 = blockIdx.x * TILE_N;
    int m0 = blockIdx.y * TILE_M;

    const int8_t* gA = g_A8 + (size_t)m0 * K_DIM;
    const int8_t* gB = g_B8 + (size_t)n0 * K_DIM;

    int acc[2][8][4];
    #pragma unroll
    for (int mb = 0; mb < 2; ++mb)
        #pragma unroll
        for (int nb = 0; nb < 8; ++nb)
            #pragma unroll
            for (int r = 0; r < 4; ++r) acc[mb][nb][r] = 0;

    // Precompute per-lane ldmatrix address components.
    // A x4 for mb block: m0=rows lo/gran lo, m1=rows hi/gran lo, m2=lo/hi, m3=hi/hi
    //   lane octet q: row = base + (q&1)*8 + r8, gran = 2*kb + (q>>1)
    uint32_t a_rowoff[2]; uint32_t a_xr[2];
    #pragma unroll
    for (int mb = 0; mb < 2; ++mb) {
        int row = wm * 32 + mb * 16 + (q & 1) * 8 + r8;
        a_rowoff[mb] = (uint32_t)(row * 64);
        a_xr[mb] = (uint32_t)((row >> 1) & 3);
    }
    int a_qh = q >> 1;
    // B x4 for nb pair p: m0=n lo/gran lo, m1=n lo/gran hi, m2=n hi/lo, m3=n hi/hi
    //   lane octet q: row = base + (q>>1)*8 + r8, gran = 2*kb + (q&1)
    uint32_t b_rowoff[4]; uint32_t b_xr[4];
    #pragma unroll
    for (int p = 0; p < 4; ++p) {
        int row = wn * 64 + p * 16 + (q >> 1) * 8 + r8;
        b_rowoff[p] = (uint32_t)(row * 64);
        b_xr[p] = (uint32_t)((row >> 1) & 3);
    }
    int b_ql = q & 1;

    // producer: 3 x 16B chunks per thread per stage (A: 1, B: 2)
    auto copy_stage = [&](int s, int kbase) {
        uint32_t sA = sbase + (uint32_t)s * STG_B;
        uint32_t sB = sA + A_STG_B;
        {
            int row = tid >> 2, gran = tid & 3;            // 512 chunks of A
            cp_async16(sA + sw16(row, gran),
                       gA + (size_t)row * K_DIM + kbase + gran * 16);
        }
        #pragma unroll
        for (int i = 0; i < 2; ++i) {
            int c = tid + i * 512;                         // 1024 chunks of B
            int row = c >> 2, gran = c & 3;
            cp_async16(sB + sw16(row, gran),
                       gB + (size_t)row * K_DIM + kbase + gran * 16);
        }
    };

    // prologue: fill STAGES-1 stages
    #pragma unroll
    for (int s = 0; s < STAGES - 1; ++s) {
        copy_stage(s, s * KS);
        cp_commit();
    }

    for (int it = 0; it < N_ITERS; ++it) {
        int s = it & (STAGES - 1);
        cp_wait_group<STAGES - 2>();
        __syncthreads();

        uint32_t sA = sbase + (uint32_t)s * STG_B;
        uint32_t sB = sA + A_STG_B;

        #pragma unroll
        for (int kb = 0; kb < 2; ++kb) {
            uint32_t af[2][4];
            #pragma unroll
            for (int mb = 0; mb < 2; ++mb) {
                uint32_t addr = sA + a_rowoff[mb]
                              + ((((uint32_t)(2 * kb + a_qh)) ^ a_xr[mb]) << 4);
                LDMATRIX_X4(af[mb][0], af[mb][1], af[mb][2], af[mb][3], addr);
            }
            uint32_t bf[4][4];
            #pragma unroll
            for (int p = 0; p < 4; ++p) {
                uint32_t addr = sB + b_rowoff[p]
                              + ((((uint32_t)(2 * kb + b_ql)) ^ b_xr[p]) << 4);
                LDMATRIX_X4(bf[p][0], bf[p][1], bf[p][2], bf[p][3], addr);
            }
            #pragma unroll
            for (int mb = 0; mb < 2; ++mb)
                #pragma unroll
                for (int nb = 0; nb < 8; ++nb)
                    mma_s8(acc[mb][nb], af[mb], &bf[nb >> 1][(nb & 1) * 2]);
        }

        // refill the stage freed this iteration
        int nxt = it + STAGES - 1;
        if (nxt < N_ITERS) copy_stage(nxt & (STAGES - 1), nxt * KS);
        cp_commit();
    }

    // ---------------- epilogue ----------------
    // out = f32( fp16_round( (acc * sx[m]) * ws[n] ) ) — bit-exact vs the
    // reference's f32-compute -> f16-cast -> f32-compare path.
    int g = lane >> 2, t = lane & 3;
    #pragma unroll
    for (int mb = 0; mb < 2; ++mb) {
        int r0 = m0 + wm * 32 + mb * 16 + g;
        float sx0 = sx[r0];
        float sx1 = sx[r0 + 8];
        #pragma unroll
        for (int nb = 0; nb < 8; ++nb) {
            int nc = n0 + wn * 64 + nb * 8 + t * 2;
            float w0 = ws[nc];
            float w1 = ws[nc + 1];
            float2 v0, v1;
            v0.x = __half2float(__float2half_rn(((float)acc[mb][nb][0] * sx0) * w0));
            v0.y = __half2float(__float2half_rn(((float)acc[mb][nb][1] * sx0) * w1));
            v1.x = __half2float(__float2half_rn(((float)acc[mb][nb][2] * sx1) * w0));
            v1.y = __half2float(__float2half_rn(((float)acc[mb][nb][3] * sx1) * w1));
            *reinterpret_cast<float2*>(out + (size_t)r0 * N_DIM + nc)       = v0;
            *reinterpret_cast<float2*>(out + (size_t)(r0 + 8) * N_DIM + nc) = v1;
        }
    }
}

// ---------------- launch ----------------
extern "C" void kernel_launch(void* const* d_in, const int* in_sizes, int n_in,
                              void* d_out, int out_size)
{
    const int*   x_q = (const int*)d_in[0];
    const float* sx  = (const float*)d_in[1];   // harness materializes f16 as f32
    const int*   wt  = (const int*)d_in[2];
    const float* ws  = (const float*)d_in[3];
    float*       out = (float*)d_out;           // __output__ dtype: float32

    cudaFuncSetAttribute(gemm_kernel,
                         cudaFuncAttributeMaxDynamicSharedMemorySize, SMEM_TOTAL);

    long long nA4 = (long long)M_DIM * (K_DIM / 2) / 4;   // 2,097,152
    long long nB4 = (long long)N_DIM * (K_DIM / 2) / 4;   // 5,636,096

    unpackA_kernel<<<(unsigned)((nA4 + 255) / 256), 256>>>(x_q, nA4);
    unpackB_kernel<<<(unsigned)((nB4 + 255) / 256), 256>>>(wt, nB4);

    dim3 grid(N_DIM / TILE_N, M_DIM / TILE_M);   // 43 x 32
    gemm_kernel<<<grid, 512, SMEM_TOTAL>>>(sx, ws, out);
}

// round 17
// speedup vs baseline: 1.0488x; 1.0029x over previous
#include <cuda_runtime.h>
#include <cuda_fp16.h>
#include <cstdint>

// ---------------- problem shape ----------------
#define M_DIM 4096
#define K_DIM 4096
#define N_DIM 11008

// int8 scratch (device globals: allocation-free scratch)
__device__ __align__(128) static int8_t g_A8[(size_t)M_DIM * K_DIM];   // 16.8 MB
__device__ __align__(128) static int8_t g_B8[(size_t)N_DIM * K_DIM];   // 45.1 MB

// ---------------- helpers ----------------
__device__ __forceinline__ uint32_t smem_to_u32(const void* smem_ptr) {
    uint32_t addr;
    asm("{ .reg .u64 tmp; cvta.to.shared.u64 tmp, %1; cvt.u32.u64 %0, tmp; }"
        : "=r"(addr) : "l"(smem_ptr));
    return addr;
}

__device__ __forceinline__ void cp_async16(uint32_t dst_smem, const void* src_gmem) {
    asm volatile("cp.async.cg.shared.global [%0], [%1], 16;"
                 :: "r"(dst_smem), "l"(src_gmem) : "memory");
}
__device__ __forceinline__ void cp_commit() {
    asm volatile("cp.async.commit_group;" ::: "memory");
}
template <int N>
__device__ __forceinline__ void cp_wait_group() {
    asm volatile("cp.async.wait_group %0;" :: "n"(N) : "memory");
}

__device__ __forceinline__ void mma_s8(int* c, const uint32_t* a, const uint32_t* b) {
    asm volatile(
        "mma.sync.aligned.m16n8k32.row.col.s32.s8.s8.s32 "
        "{%0,%1,%2,%3}, {%4,%5,%6,%7}, {%8,%9}, {%0,%1,%2,%3};"
        : "+r"(c[0]), "+r"(c[1]), "+r"(c[2]), "+r"(c[3])
        : "r"(a[0]), "r"(a[1]), "r"(a[2]), "r"(a[3]), "r"(b[0]), "r"(b[1]));
}

#define LDMATRIX_X4(r0, r1, r2, r3, addr) \
    asm volatile("ldmatrix.sync.aligned.m8n8.x4.shared.b16 {%0,%1,%2,%3}, [%4];" \
                 : "=r"(r0), "=r"(r1), "=r"(r2), "=r"(r3) : "r"(addr))

// 16B-granular swizzle over 128B rows: granule index XORed with row&7.
// 8 consecutive rows at the same logical granule hit 8 distinct 16B banks:
// conflict-free for ldmatrix 8-lane phases and cp.async writes.
__device__ __forceinline__ uint32_t sw16(int row, int gran) {
    return (uint32_t)(row * 128 + ((gran ^ (row & 7)) << 4));
}

// ---------------- unpack (fused A+B): packed int4 bytes -> int8 ----------------
static constexpr long long NA4 = (long long)M_DIM * (K_DIM / 2) / 4;   // 2,097,152
static constexpr long long NB4 = (long long)N_DIM * (K_DIM / 2) / 4;   // 5,636,096

__global__ void unpack_kernel(const int* __restrict__ inA, const int* __restrict__ inB)
{
    long long idx = (long long)blockIdx.x * blockDim.x + threadIdx.x;
    const int* in;
    int8_t* outp;
    long long i;
    if (idx < NA4) { in = inA; outp = g_A8; i = idx; }
    else if (idx < NA4 + NB4) { in = inB; outp = g_B8; i = idx - NA4; }
    else return;

    int4 v = reinterpret_cast<const int4*>(in)[i];
    int bs[4] = { v.x & 0xFF, v.y & 0xFF, v.z & 0xFF, v.w & 0xFF };
    uint32_t lo32 = 0, hi32 = 0;
    #pragma unroll
    for (int j = 0; j < 2; ++j) {
        int b = bs[j];
        int l = ((b & 0xF) ^ 8) - 8;          // sign-extended low nibble  (k even)
        int h = ((b >> 4) ^ 8) - 8;           // sign-extended high nibble (k odd)
        lo32 |= ((uint32_t)(l & 0xFF)) << (j * 16);
        lo32 |= ((uint32_t)(h & 0xFF)) << (j * 16 + 8);
    }
    #pragma unroll
    for (int j = 0; j < 2; ++j) {
        int b = bs[2 + j];
        int l = ((b & 0xF) ^ 8) - 8;
        int h = ((b >> 4) ^ 8) - 8;
        hi32 |= ((uint32_t)(l & 0xFF)) << (j * 16);
        hi32 |= ((uint32_t)(h & 0xFF)) << (j * 16 + 8);
    }
    reinterpret_cast<uint2*>(outp)[i] = make_uint2(lo32, hi32);
}

// ---------------- GEMM ----------------
// CTA tile 128(M) x 256(N), 512 threads = 16 warps (4 x 4), warp tile 32 x 64.
// K staged in 128-byte slices, 4-stage cp.async pipeline, ldmatrix fragments.
// Per iteration: barrier -> issue next-stage cp.async (overlaps mma) -> 4x k32 mma.
static constexpr int TILE_M  = 128;
static constexpr int TILE_N  = 256;
static constexpr int KS      = 128;                   // K bytes per stage
static constexpr int N_ITERS = K_DIM / KS;            // 32
static constexpr int STAGES  = 4;
static constexpr int A_STG_B = TILE_M * KS;           // 16384
static constexpr int B_STG_B = TILE_N * KS;           // 32768
static constexpr int STG_B   = A_STG_B + B_STG_B;     // 49152
static constexpr int SMEM_TOTAL = STAGES * STG_B;     // 196608

__global__ void __launch_bounds__(512, 1)
gemm_kernel(const float* __restrict__ sx, const float* __restrict__ ws,
            float* __restrict__ out)
{
    extern __shared__ char smem[];
    uint32_t sbase = smem_to_u32(smem);

    int tid  = threadIdx.x;
    int warp = tid >> 5;
    int lane = tid & 31;
    int wm = warp >> 2;          // 0..3  (M direction, 32 rows each)
    int wn = warp & 3;           // 0..3  (N direction, 64 cols each)
    int q  = lane >> 3;          // 0..3  (ldmatrix lane-octet)
    int r8 = lane & 7;

    int n0 = blockIdx.x * TILE_N;
    int m0 = blockIdx.y * TILE_M;

    const int8_t* gA = g_A8 + (size_t)m0 * K_DIM;
    const int8_t* gB = g_B8 + (size_t)n0 * K_DIM;

    int acc[2][8][4];
    #pragma unroll
    for (int mb = 0; mb < 2; ++mb)
        #pragma unroll
        for (int nb = 0; nb < 8; ++nb)
            #pragma unroll
            for (int r = 0; r < 4; ++r) acc[mb][nb][r] = 0;

    // Per-lane ldmatrix address components (row*128 and row&7 swizzle key).
    // A x4 (mb block): octet q -> row = base + (q&1)*8 + r8, gran = 2*kb + (q>>1)
    uint32_t a_rowoff[2]; uint32_t a_xr[2];
    #pragma unroll
    for (int mb = 0; mb < 2; ++mb) {
        int row = wm * 32 + mb * 16 + (q & 1) * 8 + r8;
        a_rowoff[mb] = (uint32_t)(row * 128);
        a_xr[mb] = (uint32_t)(row & 7);
    }
    int a_qh = q >> 1;
    // B x4 (nb pair p): octet q -> row = base + (q>>1)*8 + r8, gran = 2*kb + (q&1)
    uint32_t b_rowoff[4]; uint32_t b_xr[4];
    #pragma unroll
    for (int p = 0; p < 4; ++p) {
        int row = wn * 64 + p * 16 + (q >> 1) * 8 + r8;
        b_rowoff[p] = (uint32_t)(row * 128);
        b_xr[p] = (uint32_t)(row & 7);
    }
    int b_ql = q & 1;

    // producer: 6 x 16B chunks per thread per stage (A: 2, B: 4)
    auto copy_stage = [&](int s, int kbase) {
        uint32_t sA = sbase + (uint32_t)s * STG_B;
        uint32_t sB = sA + A_STG_B;
        #pragma unroll
        for (int i = 0; i < 2; ++i) {
            int c = tid + i * 512;               // 1024 chunks of A
            int row = c >> 3, gran = c & 7;
            cp_async16(sA + sw16(row, gran),
                       gA + (size_t)row * K_DIM + kbase + gran * 16);
        }
        #pragma unroll
        for (int i = 0; i < 4; ++i) {
            int c = tid + i * 512;               // 2048 chunks of B
            int row = c >> 3, gran = c & 7;
            cp_async16(sB + sw16(row, gran),
                       gB + (size_t)row * K_DIM + kbase + gran * 16);
        }
    };

    // prologue: fill STAGES-1 stages
    #pragma unroll
    for (int s = 0; s < STAGES - 1; ++s) {
        copy_stage(s, s * KS);
        cp_commit();
    }

    for (int it = 0; it < N_ITERS; ++it) {
        int s = it & (STAGES - 1);
        cp_wait_group<STAGES - 2>();
        __syncthreads();

        // Issue the refill FIRST so LDGSTS issue overlaps the mma phase.
        // Refills stage (it-1)&3, whose reads finished before the barrier above.
        int nxt = it + STAGES - 1;
        if (nxt < N_ITERS) copy_stage(nxt & (STAGES - 1), nxt * KS);
        cp_commit();

        uint32_t sA = sbase + (uint32_t)s * STG_B;
        uint32_t sB = sA + A_STG_B;

        #pragma unroll
        for (int kb = 0; kb < 4; ++kb) {
            uint32_t af[2][4];
            #pragma unroll
            for (int mb = 0; mb < 2; ++mb) {
                uint32_t addr = sA + a_rowoff[mb]
                              + ((((uint32_t)(2 * kb + a_qh)) ^ a_xr[mb]) << 4);
                LDMATRIX_X4(af[mb][0], af[mb][1], af[mb][2], af[mb][3], addr);
            }
            uint32_t bf[4][4];
            #pragma unroll
            for (int p = 0; p < 4; ++p) {
                uint32_t addr = sB + b_rowoff[p]
                              + ((((uint32_t)(2 * kb + b_ql)) ^ b_xr[p]) << 4);
                LDMATRIX_X4(bf[p][0], bf[p][1], bf[p][2], bf[p][3], addr);
            }
            #pragma unroll
            for (int mb = 0; mb < 2; ++mb)
                #pragma unroll
                for (int nb = 0; nb < 8; ++nb)
                    mma_s8(acc[mb][nb], af[mb], &bf[nb >> 1][(nb & 1) * 2]);
        }
    }

    // ---------------- epilogue ----------------
    // out = f32( fp16_round( (acc * sx[m]) * ws[n] ) ) — bit-exact vs the
    // reference's f32-compute -> f16-cast -> f32-compare path.
    int g = lane >> 2, t = lane & 3;
    #pragma unroll
    for (int mb = 0; mb < 2; ++mb) {
        int r0 = m0 + wm * 32 + mb * 16 + g;
        float sx0 = sx[r0];
        float sx1 = sx[r0 + 8];
        #pragma unroll
        for (int nb = 0; nb < 8; ++nb) {
            int nc = n0 + wn * 64 + nb * 8 + t * 2;
            float w0 = ws[nc];
            float w1 = ws[nc + 1];
            float2 v0, v1;
            v0.x = __half2float(__float2half_rn(((float)acc[mb][nb][0] * sx0) * w0));
            v0.y = __half2float(__float2half_rn(((float)acc[mb][nb][1] * sx0) * w1));
            v1.x = __half2float(__float2half_rn(((float)acc[mb][nb][2] * sx1) * w0));
            v1.y = __half2float(__float2half_rn(((float)acc[mb][nb][3] * sx1) * w1));
            *reinterpret_cast<float2*>(out + (size_t)r0 * N_DIM + nc)       = v0;
            *reinterpret_cast<float2*>(out + (size_t)(r0 + 8) * N_DIM + nc) = v1;
        }
    }
}

// ---------------- launch ----------------
extern "C" void kernel_launch(void* const* d_in, const int* in_sizes, int n_in,
                              void* d_out, int out_size)
{
    const int*   x_q = (const int*)d_in[0];
    const float* sx  = (const float*)d_in[1];   // harness materializes f16 as f32
    const int*   wt  = (const int*)d_in[2];
    const float* ws  = (const float*)d_in[3];
    float*       out = (float*)d_out;           // __output__ dtype: float32

    cudaFuncSetAttribute(gemm_kernel,
                         cudaFuncAttributeMaxDynamicSharedMemorySize, SMEM_TOTAL);

    long long ntot = NA4 + NB4;
    unpack_kernel<<<(unsigned)((ntot + 255) / 256), 256>>>(x_q, wt);

    dim3 grid(N_DIM / TILE_N, M_DIM / TILE_M);   // 43 x 32
    gemm_kernel<<<grid, 512, SMEM_TOTAL>>>(sx, ws, out);
}